// round 14
// baseline (speedup 1.0000x reference)
#include <cuda_runtime.h>

#define SEQ   4096
#define BATCH 4096
#define NIN   2
#define HID   8
#define CTAS  128
#define BPC   (BATCH / CTAS)   // 32 batches per CTA
#define TPB   (BPC * HID)      // 256 threads

typedef unsigned long long u64;

// MUFU.TANH: single-instruction tanh (sm_75+), max abs err ~2^-10.7
__device__ __forceinline__ float tanhap_(float x) {
    float y; asm("tanh.approx.f32 %0, %1;" : "=f"(y) : "f"(x)); return y;
}

// ---- Chebyshev coefficients for tanh(x)/x on y=x^2 in [0,16], u = y/8-1.
// Derived analytically from tanh(x) = sum_k 8x/(pi^2(2k-1)^2+4x^2):
// G_n = (-1)^n sum_k A_k rho_k^-n. Verified at x=0,2,2.828,4: err <= 6e-5.
#define G0  ( 0.459021f)
#define G1  (-0.298918f)
#define G2  ( 0.130657f)
#define G3  (-0.0597891f)
#define G4  ( 0.0276644f)
#define G5  (-0.0128386f)
#define G6  ( 0.00596328f)
#define G7  (-0.00277049f)
#define G8  ( 0.00128723f)
#define G9  (-0.00059810f)
#define G10 ( 0.00027790f)
#define G11 (-0.00012913f)
#define G12 ( 0.00005999f)

// Pack two floats into a b64 register pair.
__device__ __forceinline__ u64 pk2(float lo, float hi) {
    u64 d;
    asm("mov.b64 %0, {%1, %2};" : "=l"(d)
        : "r"(__float_as_uint(lo)), "r"(__float_as_uint(hi)));
    return d;
}
__device__ __forceinline__ void upk2(u64 v, float& lo, float& hi) {
    unsigned a, b;
    asm("mov.b64 {%0, %1}, %2;" : "=r"(a), "=r"(b) : "l"(v));
    lo = __uint_as_float(a); hi = __uint_as_float(b);
}

// Packed fp32x2 ops on b64 carriers — single SASS instruction each.
__device__ __forceinline__ u64 ffma2(u64 a, u64 b, u64 c) {
    u64 d; asm("fma.rn.f32x2 %0, %1, %2, %3;" : "=l"(d) : "l"(a), "l"(b), "l"(c)); return d;
}
__device__ __forceinline__ u64 fmul2(u64 a, u64 b) {
    u64 d; asm("mul.rn.f32x2 %0, %1, %2;" : "=l"(d) : "l"(a), "l"(b)); return d;
}
__device__ __forceinline__ u64 fadd2(u64 a, u64 b) {
    u64 d; asm("add.rn.f32x2 %0, %1, %2;" : "=l"(d) : "l"(a), "l"(b)); return d;
}

// Chebyshev-basis tanh: tanh(c) = clamp(c,-4,4) * sum_n G_n T_n(u),
// u = clamp(c^2/8 - 1, <=1). All FMA-pipe; T's built by the doubling
// identities T_{m+n} = 2 T_m T_n - T_{|m-n|}; |T_n|<=1 (numerically safe).
__device__ __forceinline__ float tanh_cheb(float c) {
    float cc = fminf(fmaxf(c, -4.0f), 4.0f);   // off critical path until the end
    float y  = c * c;
    float u  = fminf(fmaf(y, 0.125f, -1.0f), 1.0f);
    float tu  = u + u;
    float T2  = fmaf(tu, u, -1.0f);
    float tT2 = T2 + T2;
    float T3  = fmaf(tT2, u, -u);          // 2*T2*u - T1
    float T4  = fmaf(tT2, T2, -1.0f);      // 2*T2^2 - 1
    float tT3 = T3 + T3;
    float tT4 = T4 + T4;
    float T5  = fmaf(tT2, T3, -u);         // 2*T2*T3 - T1
    float T6  = fmaf(tT3, T3, -1.0f);      // 2*T3^2 - 1
    float T7  = fmaf(tT3, T4, -u);         // 2*T3*T4 - T1
    float T8  = fmaf(tT4, T4, -1.0f);      // 2*T4^2 - 1
    float tT5 = T5 + T5;
    float T9  = fmaf(tT4, T5, -u);         // 2*T4*T5 - T1
    float T10 = fmaf(tT5, T5, -1.0f);      // 2*T5^2 - 1
    float T11 = fmaf(tT5, T6, -u);         // 2*T5*T6 - T1
    float T12 = fmaf(tT4, T8, -T4);        // 2*T4*T8 - T4

    // 4-lane dot product, combined with a 2-level add tree.
    float L0 = fmaf(G4, T4, G0);
    L0 = fmaf(G8,  T8,  L0);
    L0 = fmaf(G12, T12, L0);
    float L1 = G1 * u;
    L1 = fmaf(G5, T5, L1);
    L1 = fmaf(G9, T9, L1);
    float L2 = G2 * T2;
    L2 = fmaf(G6,  T6,  L2);
    L2 = fmaf(G10, T10, L2);
    float L3 = G3 * T3;
    L3 = fmaf(G7,  T7,  L3);
    L3 = fmaf(G11, T11, L3);
    float S = (L0 + L1) + (L2 + L3);
    return cc * S;
}

// Compiler-only memory fence (no WARPSYNC emitted). Same-warp LSU ordering
// guarantees the hoisted LDS sees all lanes' preceding STS (proven R9/R11).
__device__ __forceinline__ void memfence_compiler() {
    asm volatile("" ::: "memory");
}

__global__ void __launch_bounds__(TPB) lstm_kernel(
    const float* __restrict__ x,
    const float* __restrict__ h0,
    const float* __restrict__ c0,
    const float* __restrict__ W_ih,
    const float* __restrict__ W_hh,
    const float* __restrict__ b_ih,
    const float* __restrict__ b_hh,
    float* __restrict__ out)
{
    const int tid = threadIdx.x;
    const int g   = tid >> 3;   // batch group within CTA
    const int j   = tid & 7;    // h index within batch
    const int b   = blockIdx.x * BPC + g;

    // Gate rows owned by this lane (PyTorch order i,f,g,o)
    const int ri = j, rf = 8 + j, rg = 16 + j, ro = 24 + j;
    // sigmoid(u) = 0.5*tanh(u/2)+0.5 -> fold the 1/2 into rows i,f,o.
    const float si = 0.5f, sf = 0.5f, sg = 1.0f, so = 0.5f;

    // Pair-packed weights as b64 carriers: (i,g) pair and (f,o) pair.
    u64 wig_h[HID], wfo_h[HID];
    #pragma unroll
    for (int k = 0; k < HID; k++) {
        wig_h[k] = pk2(si * W_hh[ri * HID + k], sg * W_hh[rg * HID + k]);
        wfo_h[k] = pk2(sf * W_hh[rf * HID + k], so * W_hh[ro * HID + k]);
    }
    const u64 wig_x0 = pk2(si * W_ih[ri * NIN + 0], sg * W_ih[rg * NIN + 0]);
    const u64 wig_x1 = pk2(si * W_ih[ri * NIN + 1], sg * W_ih[rg * NIN + 1]);
    const u64 wfo_x0 = pk2(sf * W_ih[rf * NIN + 0], so * W_ih[ro * NIN + 0]);
    const u64 wfo_x1 = pk2(sf * W_ih[rf * NIN + 1], so * W_ih[ro * NIN + 1]);
    const u64 big = pk2(si * (b_ih[ri] + b_hh[ri]), sg * (b_ih[rg] + b_hh[rg]));
    const u64 bfo = pk2(sf * (b_ih[rf] + b_hh[rf]), so * (b_ih[ro] + b_hh[ro]));

    // h exchange: duplicated (h,h) pairs, SINGLE buffer, software-pipelined
    // one step ahead (LDS issued right after the STS; consumed next step).
    __shared__ __align__(16) u64 sh[BPC][HID];

    float c = c0[b * HID + j];
    float h = h0[b * HID + j];

    const size_t xstride = (size_t)BATCH * NIN;
    const float* xbase = x + (size_t)b * NIN;
    auto ldx = [&](int s) -> float2 {
        int sc = s < SEQ ? s : (SEQ - 1);
        return *(const float2*)(xbase + (size_t)sc * xstride);
    };

    // x-projection (bias + W_ih*x), off the recurrence chain.
    auto xproj = [&](float2 xv, u64& pig, u64& pfo) {
        u64 x0d = pk2(xv.x, xv.x);
        u64 x1d = pk2(xv.y, xv.y);
        pig = ffma2(wig_x1, x1d, ffma2(wig_x0, x0d, big));
        pfo = ffma2(wfo_x1, x1d, ffma2(wfo_x0, x0d, bfo));
    };

    // Prologue: publish h(0), pre-load pipeline registers.
    sh[g][j] = pk2(h, h);
    __syncwarp();
    ulonglong2 P0, P1, P2, P3;
    {
        const ulonglong2* hp = (const ulonglong2*)&sh[g][0];
        P0 = hp[0]; P1 = hp[1]; P2 = hp[2]; P3 = hp[3];
    }

    // 8-deep x prefetch for the 8x-unrolled loop.
    float2 xq0 = ldx(1), xq1 = ldx(2), xq2 = ldx(3), xq3 = ldx(4);
    float2 xq4 = ldx(5), xq5 = ldx(6), xq6 = ldx(7), xq7 = ldx(8);
    u64 xpig, xpfo;
    xproj(ldx(0), xpig, xpfo);

    auto dostep = [&](float2 xnext) {
        // Consume h pairs whose LDS was issued at the end of the previous step.
        ulonglong2 p0 = P0, p1 = P1, p2 = P2, p3 = P3;

        float hc = 0.5f * c;   // off-chain half*c

        // Four-way accumulation trees per gate-pair (depth 2 FFMA2 + 2 fadd2)
        u64 aA = ffma2(wig_h[0], p0.x, xpig);
        u64 gA = ffma2(wfo_h[0], p0.x, xpfo);
        u64 aB = fmul2(wig_h[1], p0.y);
        u64 gB = fmul2(wfo_h[1], p0.y);
        u64 aC = fmul2(wig_h[2], p1.x);
        u64 gC = fmul2(wfo_h[2], p1.x);
        u64 aD = fmul2(wig_h[3], p1.y);
        u64 gD = fmul2(wfo_h[3], p1.y);
        aA = ffma2(wig_h[4], p2.x, aA);  gA = ffma2(wfo_h[4], p2.x, gA);
        aB = ffma2(wig_h[5], p2.y, aB);  gB = ffma2(wfo_h[5], p2.y, gB);
        aC = ffma2(wig_h[6], p3.x, aC);  gC = ffma2(wfo_h[6], p3.x, gC);
        aD = ffma2(wig_h[7], p3.y, aD);  gD = ffma2(wfo_h[7], p3.y, gD);
        u64 aAB = fadd2(aA, aB);
        u64 gAB = fadd2(gA, gB);
        u64 aCD = fadd2(aC, aD);
        u64 gCD = fadd2(gC, gD);
        u64 Aig = fadd2(aAB, aCD);
        u64 Afo = fadd2(gAB, gCD);

        float a_i, a_g, a_f, a_o;
        upk2(Aig, a_i, a_g);
        upk2(Afo, a_f, a_o);

        // Gate tanhs: the ONLY MUFU round-trip left (4 issues).
        float t_i = tanhap_(a_i);   // a_i = u_i/2
        float t_g = tanhap_(a_g);   // true tanh(g)
        float t_f = tanhap_(a_f);
        float t_o = tanhap_(a_o);

        // c = 0.5*t_f*c + (0.5*c + s_i*t_g), s_i = 0.5*t_i + 0.5
        float s_i = fmaf(0.5f, t_i, 0.5f);
        float q   = fmaf(s_i, t_g, hc);
        c = fmaf(hc, t_f, q);
        float s_o = fmaf(0.5f, t_o, 0.5f);

        // h = s_o * tanh(c): Chebyshev-basis polynomial on the FMA pipe —
        // replaces the second MUFU round-trip (~85 cyc) with a ~60-cyc chain.
        h = s_o * tanh_cheb(c);

        // Publish h and IMMEDIATELY issue next step's exchange loads;
        // the LDS round-trip overlaps xproj + loop overhead (proven R11).
        sh[g][j] = pk2(h, h);
        memfence_compiler();
        {
            const ulonglong2* hp = (const ulonglong2*)&sh[g][0];
            P0 = hp[0]; P1 = hp[1]; P2 = hp[2]; P3 = hp[3];
        }

        // Fill window: next step's x projection (off the recurrence chain)
        u64 nig, nfo;
        xproj(xnext, nig, nfo);
        xpig = nig; xpfo = nfo;
    };

    #pragma unroll 1
    for (int s = 0; s < SEQ; s += 8) {
        dostep(xq0);  xq0 = ldx(s + 9);
        dostep(xq1);  xq1 = ldx(s + 10);
        dostep(xq2);  xq2 = ldx(s + 11);
        dostep(xq3);  xq3 = ldx(s + 12);
        dostep(xq4);  xq4 = ldx(s + 13);
        dostep(xq5);  xq5 = ldx(s + 14);
        dostep(xq6);  xq6 = ldx(s + 15);
        dostep(xq7);  xq7 = ldx(s + 16);
    }

    out[b * HID + j] = h;
}

extern "C" void kernel_launch(void* const* d_in, const int* in_sizes, int n_in,
                              void* d_out, int out_size) {
    const float* x    = (const float*)d_in[0];
    const float* h0   = (const float*)d_in[1];
    const float* c0   = (const float*)d_in[2];
    const float* W_ih = (const float*)d_in[3];
    const float* W_hh = (const float*)d_in[4];
    const float* b_ih = (const float*)d_in[5];
    const float* b_hh = (const float*)d_in[6];
    lstm_kernel<<<CTAS, TPB>>>(x, h0, c0, W_ih, W_hh, b_ih, b_hh, (float*)d_out);
}

// round 15
// speedup vs baseline: 1.2042x; 1.2042x over previous
#include <cuda_runtime.h>

#define SEQ   4096
#define BATCH 4096
#define NIN   2
#define HID   8
#define CTAS  128
#define BPC   (BATCH / CTAS)   // 32 batches per CTA
#define TPB   (BPC * HID)      // 256 threads

typedef unsigned long long u64;

// MUFU.TANH: single-instruction tanh (sm_75+), max abs err ~2^-10.7
__device__ __forceinline__ float tanhap_(float x) {
    float y; asm("tanh.approx.f32 %0, %1;" : "=f"(y) : "f"(x)); return y;
}

// Pack two floats into a b64 register pair.
__device__ __forceinline__ u64 pk2(float lo, float hi) {
    u64 d;
    asm("mov.b64 %0, {%1, %2};" : "=l"(d)
        : "r"(__float_as_uint(lo)), "r"(__float_as_uint(hi)));
    return d;
}
__device__ __forceinline__ void upk2(u64 v, float& lo, float& hi) {
    unsigned a, b;
    asm("mov.b64 {%0, %1}, %2;" : "=r"(a), "=r"(b) : "l"(v));
    lo = __uint_as_float(a); hi = __uint_as_float(b);
}

// Packed fp32x2 ops on b64 carriers — single SASS instruction each.
__device__ __forceinline__ u64 ffma2(u64 a, u64 b, u64 c) {
    u64 d; asm("fma.rn.f32x2 %0, %1, %2, %3;" : "=l"(d) : "l"(a), "l"(b), "l"(c)); return d;
}
__device__ __forceinline__ u64 fmul2(u64 a, u64 b) {
    u64 d; asm("mul.rn.f32x2 %0, %1, %2;" : "=l"(d) : "l"(a), "l"(b)); return d;
}
__device__ __forceinline__ u64 fadd2(u64 a, u64 b) {
    u64 d; asm("add.rn.f32x2 %0, %1, %2;" : "=l"(d) : "l"(a), "l"(b)); return d;
}

// Compiler-only memory fence (no WARPSYNC emitted). Same-warp LSU ordering
// guarantees the hoisted LDS sees all lanes' preceding STS (proven R9/R11).
__device__ __forceinline__ void memfence_compiler() {
    asm volatile("" ::: "memory");
}

__global__ void __launch_bounds__(TPB) lstm_kernel(
    const float* __restrict__ x,
    const float* __restrict__ h0,
    const float* __restrict__ c0,
    const float* __restrict__ W_ih,
    const float* __restrict__ W_hh,
    const float* __restrict__ b_ih,
    const float* __restrict__ b_hh,
    float* __restrict__ out)
{
    const int tid = threadIdx.x;
    const int g   = tid >> 3;   // batch group within CTA
    const int j   = tid & 7;    // h index within batch
    const int b   = blockIdx.x * BPC + g;

    // Gate rows owned by this lane (PyTorch order i,f,g,o)
    const int ri = j, rf = 8 + j, rg = 16 + j, ro = 24 + j;
    // sigmoid(u) = 0.5*tanh(u/2)+0.5 -> fold the 1/2 into rows i,f,o.
    const float si = 0.5f, sf = 0.5f, sg = 1.0f, so = 0.5f;

    // Pair-packed weights as b64 carriers: (i,g) pair and (f,o) pair.
    u64 wig_h[HID], wfo_h[HID];
    #pragma unroll
    for (int k = 0; k < HID; k++) {
        wig_h[k] = pk2(si * W_hh[ri * HID + k], sg * W_hh[rg * HID + k]);
        wfo_h[k] = pk2(sf * W_hh[rf * HID + k], so * W_hh[ro * HID + k]);
    }
    const u64 wig_x0 = pk2(si * W_ih[ri * NIN + 0], sg * W_ih[rg * NIN + 0]);
    const u64 wig_x1 = pk2(si * W_ih[ri * NIN + 1], sg * W_ih[rg * NIN + 1]);
    const u64 wfo_x0 = pk2(sf * W_ih[rf * NIN + 0], so * W_ih[ro * NIN + 0]);
    const u64 wfo_x1 = pk2(sf * W_ih[rf * NIN + 1], so * W_ih[ro * NIN + 1]);
    const u64 big = pk2(si * (b_ih[ri] + b_hh[ri]), sg * (b_ih[rg] + b_hh[rg]));
    const u64 bfo = pk2(sf * (b_ih[rf] + b_hh[rf]), so * (b_ih[ro] + b_hh[ro]));

    // h exchange: duplicated (h,h) pairs, SINGLE buffer, software-pipelined
    // one step ahead (LDS issued right after the STS; consumed next step).
    __shared__ __align__(16) u64 sh[BPC][HID];

    float c = c0[b * HID + j];
    float h = h0[b * HID + j];

    const size_t xstride = (size_t)BATCH * NIN;
    const float* xbase = x + (size_t)b * NIN;
    auto ldx = [&](int s) -> float2 {
        int sc = s < SEQ ? s : (SEQ - 1);
        return *(const float2*)(xbase + (size_t)sc * xstride);
    };

    // Prologue: publish h(0), pre-load pipeline registers.
    sh[g][j] = pk2(h, h);
    __syncwarp();
    ulonglong2 P0, P1, P2, P3;
    {
        const ulonglong2* hp = (const ulonglong2*)&sh[g][0];
        P0 = hp[0]; P1 = hp[1]; P2 = hp[2]; P3 = hp[3];
    }

    // 8-deep x prefetch for the 8x-unrolled loop.
    float2 xq0 = ldx(1), xq1 = ldx(2), xq2 = ldx(3), xq3 = ldx(4);
    float2 xq4 = ldx(5), xq5 = ldx(6), xq6 = ldx(7), xq7 = ldx(8);
    u64 xpig, xpfo;
    {
        float2 x0 = ldx(0);
        u64 x0d = pk2(x0.x, x0.x);
        u64 x1d = pk2(x0.y, x0.y);
        xpig = ffma2(wig_x1, x1d, ffma2(wig_x0, x0d, big));
        xpfo = ffma2(wfo_x1, x1d, ffma2(wfo_x0, x0d, bfo));
    }

    // One step. xnext: x[s+1] (already prefetched). xfar: slot to refill
    // from GMEM 8 steps ahead — issued inside the gate-RT window.
    auto dostep = [&](float2 xnext, float2& xfar, int sfar) {
        // Consume h pairs whose LDS was issued at the end of the previous step.
        ulonglong2 p0 = P0, p1 = P1, p2 = P2, p3 = P3;

        float hc = 0.5f * c;   // off-chain half*c

        // Four-way accumulation trees per gate-pair (depth 2 FFMA2 + 2 fadd2)
        u64 aA = ffma2(wig_h[0], p0.x, xpig);
        u64 gA = ffma2(wfo_h[0], p0.x, xpfo);
        u64 aB = fmul2(wig_h[1], p0.y);
        u64 gB = fmul2(wfo_h[1], p0.y);
        u64 aC = fmul2(wig_h[2], p1.x);
        u64 gC = fmul2(wfo_h[2], p1.x);
        u64 aD = fmul2(wig_h[3], p1.y);
        u64 gD = fmul2(wfo_h[3], p1.y);
        aA = ffma2(wig_h[4], p2.x, aA);  gA = ffma2(wfo_h[4], p2.x, gA);
        aB = ffma2(wig_h[5], p2.y, aB);  gB = ffma2(wfo_h[5], p2.y, gB);
        aC = ffma2(wig_h[6], p3.x, aC);  gC = ffma2(wfo_h[6], p3.x, gC);
        aD = ffma2(wig_h[7], p3.y, aD);  gD = ffma2(wfo_h[7], p3.y, gD);
        u64 aAB = fadd2(aA, aB);
        u64 gAB = fadd2(gA, gB);
        u64 aCD = fadd2(aC, aD);
        u64 gCD = fadd2(gC, gD);
        u64 Aig = fadd2(aAB, aCD);
        u64 Afo = fadd2(gAB, gCD);

        float a_i, a_g, a_f, a_o;
        upk2(Aig, a_i, a_g);
        upk2(Afo, a_f, a_o);

        // Gate tanhs, issue order i,g,f,o (c waits on f; o trails for free).
        float t_i = tanhap_(a_i);   // a_i = u_i/2
        float t_g = tanhap_(a_g);   // true tanh(g)
        float t_f = tanhap_(a_f);
        float t_o = tanhap_(a_o);

        // ---- Gate-RT window fill: next x-projection leg A + far prefetch.
        u64 x0d = pk2(xnext.x, xnext.x);
        u64 x1d = pk2(xnext.y, xnext.y);
        u64 t1 = ffma2(wig_x0, x0d, big);
        u64 t2 = ffma2(wfo_x0, x0d, bfo);
        xfar = ldx(sfar);           // GMEM prefetch, pure latency overlap

        // c = 0.5*t_f*c + (0.5*c + s_i*t_g), s_i = 0.5*t_i + 0.5
        float s_i = fmaf(0.5f, t_i, 0.5f);
        float q   = fmaf(s_i, t_g, hc);
        c = fmaf(hc, t_f, q);

        float t_c = tanhap_(c);     // second MUFU round-trip

        // ---- tanhc-RT window fill: x-projection leg B.
        u64 nig = ffma2(wig_x1, x1d, t1);
        u64 nfo = ffma2(wfo_x1, x1d, t2);

        float s_o = fmaf(0.5f, t_o, 0.5f);
        h = s_o * t_c;

        // Publish h and IMMEDIATELY issue next step's exchange loads;
        // the LDS round-trip overlaps the handoff + loop overhead (R11).
        sh[g][j] = pk2(h, h);
        memfence_compiler();
        {
            const ulonglong2* hp = (const ulonglong2*)&sh[g][0];
            P0 = hp[0]; P1 = hp[1]; P2 = hp[2]; P3 = hp[3];
        }

        xpig = nig; xpfo = nfo;
    };

    #pragma unroll 1
    for (int s = 0; s < SEQ; s += 8) {
        dostep(xq0, xq0, s + 9);
        dostep(xq1, xq1, s + 10);
        dostep(xq2, xq2, s + 11);
        dostep(xq3, xq3, s + 12);
        dostep(xq4, xq4, s + 13);
        dostep(xq5, xq5, s + 14);
        dostep(xq6, xq6, s + 15);
        dostep(xq7, xq7, s + 16);
    }

    out[b * HID + j] = h;
}

extern "C" void kernel_launch(void* const* d_in, const int* in_sizes, int n_in,
                              void* d_out, int out_size) {
    const float* x    = (const float*)d_in[0];
    const float* h0   = (const float*)d_in[1];
    const float* c0   = (const float*)d_in[2];
    const float* W_ih = (const float*)d_in[3];
    const float* W_hh = (const float*)d_in[4];
    const float* b_ih = (const float*)d_in[5];
    const float* b_hh = (const float*)d_in[6];
    lstm_kernel<<<CTAS, TPB>>>(x, h0, c0, W_ih, W_hh, b_ih, b_hh, (float*)d_out);
}